// round 6
// baseline (speedup 1.0000x reference)
#include <cuda_runtime.h>

#define Bb 8
#define Nn 16384
#define Kk 256
#define Dd 20
#define DE 21            // Dd + folded msq row

#define TP 32            // pixels per tile (4 per warp, 8 warps)
#define PPB 128          // pixels per block
#define NTILES (PPB/TP)  // 4
#define CH (Nn/PPB)      // 128 chunks per batch

#define EM (Bb*Kk*Dd)    // 40960
#define ES (Bb*Kk)       // 2048
#define G1 8             // stage-1 reduction groups
#define CPG (CH/G1)      // 16 chunks per group

// Per-(chunk,batch,k) partials. Plain stores -> deterministic reductions.
__device__ float g_partM[(long)CH * EM];   // ~21 MB
__device__ float g_partS[CH * ES];         // ~1 MB
__device__ float g_p2M[G1 * EM];
__device__ float g_p2S[G1 * ES];

// mean_ext(21*256) + f_sm(640) + f_dup(32*42) + rinv(32) + p_sm(8192)
#define SMEM_FLOATS (DE*Kk + TP*Dd + TP*2*DE + TP + TP*Kk)   // 15584

// ---- Blackwell packed f32x2 helpers ----
typedef unsigned long long u64;

__device__ __forceinline__ u64 pack2(float v) {          // broadcast {v,v}
    u64 r; asm("mov.b64 %0, {%1,%1};" : "=l"(r) : "f"(v)); return r;
}
__device__ __forceinline__ u64 ffma2(u64 a, u64 b, u64 c) {
    u64 d; asm("fma.rn.f32x2 %0, %1, %2, %3;" : "=l"(d) : "l"(a), "l"(b), "l"(c));
    return d;
}
__device__ __forceinline__ void unpk(u64 v, float& lo, float& hi) {
    asm("mov.b64 {%0,%1}, %2;" : "=f"(lo), "=f"(hi) : "l"(v));
}

__global__ __launch_bounds__(256, 3)
void em_main(const float* __restrict__ gmean,
             const float* __restrict__ gfeat,
             const float* __restrict__ gvalid,
             const float* __restrict__ gadj)
{
    extern __shared__ float sm[];
    float* mean_sm = sm;                    // [DE][Kk]: rows 0..19 mean^T, row 20 = msq
    float* f_sm    = mean_sm + DE * Kk;     // [TP][Dd]     natural (Phase B)
    float* f_dup   = f_sm + TP * Dd;        // [TP][2*DE]   {f,f} pairs; [20]={-.5,-.5}
    float* rinv_sm = f_dup + TP * 2 * DE;   // [TP]
    float* p_sm    = rinv_sm + TP;          // [TP][Kk]     unnormalized e

    const int tid = threadIdx.x;
    const int kg  = tid & 31;          // lane
    const int w   = tid >> 5;          // warp 0..7; owns pixels 4w..4w+3
    const int b   = blockIdx.y;
    const int ch  = blockIdx.x;
    const int n0  = ch * PPB;
    const long vdelta = gadj - gvalid; // constant pointer diff

    // ---- stage mean[b] transposed [d][k]; row 20 = |m|^2 ----
    const float* mb = gmean + (long)b * Kk * Dd;
    for (int i = tid; i < Kk * Dd; i += 256) {
        int k = i / Dd, d = i - k * Dd;
        mean_sm[d * Kk + k] = mb[i];
    }
    __syncthreads();
    {
        float s = 0.f;
#pragma unroll
        for (int d = 0; d < Dd; d++) { float m = mean_sm[d * Kk + tid]; s += m * m; }
        mean_sm[Dd * Kk + tid] = s;    // msq row
    }

    // Phase-B accumulators: thread owns k = tid, packed pairs over d
    u64 macc2[Dd / 2];
#pragma unroll
    for (int q = 0; q < Dd / 2; q++) macc2[q] = 0ULL;
    float sacc = 0.f;

    for (int t = 0; t < NTILES; t++) {
        const int nbase = n0 + t * TP;
        __syncthreads();   // msq row ready (t=0) / previous Phase B done

        // ---- cooperative feature-tile load; build duplicated copy ----
        if (tid < TP * Dd / 4) {
            float4 fv = ((const float4*)(gfeat + ((long)b * Nn + nbase) * Dd))[tid];
            ((float4*)f_sm)[tid] = fv;
            const int e0 = 4 * tid;
            const int px = e0 / Dd, d0 = e0 - px * Dd;   // float4 never spans pixels
            float* fd = &f_dup[px * (2 * DE) + 2 * d0];
            ((float2*)fd)[0] = make_float2(fv.x, fv.x);
            ((float2*)fd)[1] = make_float2(fv.y, fv.y);
            ((float2*)fd)[2] = make_float2(fv.z, fv.z);
            ((float2*)fd)[3] = make_float2(fv.w, fv.w);
        }
        if (tid < TP)   // msq coupling coefficient at d=20
            *(float2*)&f_dup[tid * (2 * DE) + 2 * Dd] = make_float2(-0.5f, -0.5f);
        __syncthreads();

        // ===== Phase A: two passes of 2 pixels =====
        const int p0 = 4 * w;
        float s4[4];
#pragma unroll
        for (int pass = 0; pass < 2; pass++) {
            const int pa = p0 + 2 * pass;
            const float* vr = gvalid + ((long)b * Nn + nbase + pa) * Kk;

            // px_a valid/adjust: issued now, hidden under the dot loop
            float4 va0 = *(const float4*)(vr + 4 * kg);
            float4 va1 = *(const float4*)(vr + 128 + 4 * kg);
            float4 aa0 = *(const float4*)(vr + vdelta + 4 * kg);
            float4 aa1 = *(const float4*)(vr + vdelta + 128 + 4 * kg);

            u64 dotA[4], dotB[4];
#pragma unroll
            for (int j = 0; j < 4; j++) { dotA[j] = 0ULL; dotB[j] = 0ULL; }
            u64 fsqA = 0ULL, fsqB = 0ULL;

            const float* fdA = &f_dup[pa * (2 * DE)];
            const float* fdB = &f_dup[(pa + 1) * (2 * DE)];
#pragma unroll
            for (int d = 0; d < DE; d++) {
                ulonglong2 m0 = *(const ulonglong2*)&mean_sm[d * Kk + 4 * kg];
                ulonglong2 m1 = *(const ulonglong2*)&mean_sm[d * Kk + 128 + 4 * kg];
                const u64 fA = *(const u64*)&fdA[2 * d];
                const u64 fB = *(const u64*)&fdB[2 * d];
                if (d < Dd) {            // |f|^2 excludes the msq row
                    fsqA = ffma2(fA, fA, fsqA);
                    fsqB = ffma2(fB, fB, fsqB);
                }
                dotA[0] = ffma2(m0.x, fA, dotA[0]);
                dotA[1] = ffma2(m0.y, fA, dotA[1]);
                dotA[2] = ffma2(m1.x, fA, dotA[2]);
                dotA[3] = ffma2(m1.y, fA, dotA[3]);
                dotB[0] = ffma2(m0.x, fB, dotB[0]);
                dotB[1] = ffma2(m0.y, fB, dotB[1]);
                dotB[2] = ffma2(m1.x, fB, dotB[2]);
                dotB[3] = ffma2(m1.y, fB, dotB[3]);
            }

            // px_b valid/adjust: issued now, hidden under px_a epilogue
            const float* vrb = vr + Kk;
            float4 vb0 = *(const float4*)(vrb + 4 * kg);
            float4 vb1 = *(const float4*)(vrb + 128 + 4 * kg);
            float4 ab0 = *(const float4*)(vrb + vdelta + 4 * kg);
            float4 ab1 = *(const float4*)(vrb + vdelta + 128 + 4 * kg);

            // ---- px_a epilogue ----
            {
                float dv[8];
                unpk(dotA[0], dv[0], dv[1]);
                unpk(dotA[1], dv[2], dv[3]);
                unpk(dotA[2], dv[4], dv[5]);
                unpk(dotA[3], dv[6], dv[7]);
                float c, chi; unpk(fsqA, c, chi);
                float va[8] = {va0.x, va0.y, va0.z, va0.w, va1.x, va1.y, va1.z, va1.w};
                float aa[8] = {aa0.x, aa0.y, aa0.z, aa0.w, aa1.x, aa1.y, aa1.z, aa1.w};
                float e[8];
                float s = 0.f;
#pragma unroll
                for (int j = 0; j < 8; j++) {
                    float dist = fmaf(-2.f, dv[j], c);         // msq already folded in
                    e[j] = __expf(fmaf(dist, -va[j], -aa[j]));
                    s += e[j];
                }
                s4[2 * pass] = s;
                *(float4*)&p_sm[pa * Kk + 4 * kg] = make_float4(e[0], e[1], e[2], e[3]);
                *(float4*)&p_sm[pa * Kk + 128 + 4 * kg] = make_float4(e[4], e[5], e[6], e[7]);
            }
            // ---- px_b epilogue ----
            {
                float dv[8];
                unpk(dotB[0], dv[0], dv[1]);
                unpk(dotB[1], dv[2], dv[3]);
                unpk(dotB[2], dv[4], dv[5]);
                unpk(dotB[3], dv[6], dv[7]);
                float c, chi; unpk(fsqB, c, chi);
                float va[8] = {vb0.x, vb0.y, vb0.z, vb0.w, vb1.x, vb1.y, vb1.z, vb1.w};
                float aa[8] = {ab0.x, ab0.y, ab0.z, ab0.w, ab1.x, ab1.y, ab1.z, ab1.w};
                float e[8];
                float s = 0.f;
#pragma unroll
                for (int j = 0; j < 8; j++) {
                    float dist = fmaf(-2.f, dv[j], c);
                    e[j] = __expf(fmaf(dist, -va[j], -aa[j]));
                    s += e[j];
                }
                s4[2 * pass + 1] = s;
                *(float4*)&p_sm[(pa + 1) * Kk + 4 * kg] = make_float4(e[0], e[1], e[2], e[3]);
                *(float4*)&p_sm[(pa + 1) * Kk + 128 + 4 * kg] = make_float4(e[4], e[5], e[6], e[7]);
            }
        }

        // 4 interleaved butterfly sums
#pragma unroll
        for (int o = 16; o > 0; o >>= 1) {
            s4[0] += __shfl_xor_sync(0xffffffffu, s4[0], o);
            s4[1] += __shfl_xor_sync(0xffffffffu, s4[1], o);
            s4[2] += __shfl_xor_sync(0xffffffffu, s4[2], o);
            s4[3] += __shfl_xor_sync(0xffffffffu, s4[3], o);
        }
        if (kg < 4) {
            float sv = (kg == 0) ? s4[0] : (kg == 1) ? s4[1] : (kg == 2) ? s4[2] : s4[3];
            rinv_sm[p0 + kg] = __fdividef(1.f, sv);
        }
        __syncthreads();

        // ============ Phase B: accumulate M[k][:] and S[k] (packed) ============
#pragma unroll
        for (int p4 = 0; p4 < TP / 4; p4++) {
            const float4 rv = *(const float4*)&rinv_sm[4 * p4];
            const float rvs[4] = {rv.x, rv.y, rv.z, rv.w};
#pragma unroll
            for (int pi = 0; pi < 4; pi++) {
                const int p = 4 * p4 + pi;
                const float pv = p_sm[p * Kk + tid] * rvs[pi];
                sacc += pv;
                const u64 pp = pack2(pv);
                const ulonglong2* f2 = (const ulonglong2*)&f_sm[p * Dd];
#pragma unroll
                for (int q = 0; q < 5; q++) {
                    ulonglong2 u = f2[q];
                    macc2[2 * q]     = ffma2(u.x, pp, macc2[2 * q]);
                    macc2[2 * q + 1] = ffma2(u.y, pp, macc2[2 * q + 1]);
                }
            }
        }
    }

    // ---- coalesced per-(chunk,b,k) partials ----
    const int bk = (b << 8) | tid;            // b*Kk + k
    g_partS[ch * ES + bk] = sacc;
    float* pm = &g_partM[(long)ch * EM + (long)bk * Dd];
#pragma unroll
    for (int q = 0; q < Dd / 2; q++) {
        float lo, hi;
        unpk(macc2[q], lo, hi);
        pm[2 * q] = lo;  pm[2 * q + 1] = hi;
    }
}

// Stage 1: fold 128 chunks -> 8 groups, fully coalesced (thread = element).
__global__ void reduce1()
{
    const int i = blockIdx.x * 256 + threadIdx.x;
    if (i < G1 * EM) {
        const int g = i / EM, e = i - g * EM;
        float s = 0.f;
#pragma unroll 4
        for (int c = 0; c < CPG; c++)
            s += g_partM[(long)(g * CPG + c) * EM + e];
        g_p2M[i] = s;
    } else {
        const int j = i - G1 * EM;
        if (j < G1 * ES) {
            const int g = j / ES, e = j - g * ES;
            float s = 0.f;
#pragma unroll 4
            for (int c = 0; c < CPG; c++)
                s += g_partS[(g * CPG + c) * ES + e];
            g_p2S[j] = s;
        }
    }
}

// Stage 2: final 8-way sum + normalize.
__global__ void reduce2(float* __restrict__ out)
{
    const int e = blockIdx.x * 256 + threadIdx.x;   // over EM = 40960
    if (e >= EM) return;
    const int bk = e / Dd;
    float m = 0.f, s = 0.f;
#pragma unroll
    for (int g = 0; g < G1; g++) {
        m += g_p2M[g * EM + e];
        s += g_p2S[g * ES + bk];
    }
    out[e] = m / fmaxf(s, 1e-12f);
}

extern "C" void kernel_launch(void* const* d_in, const int* in_sizes, int n_in,
                              void* d_out, int out_size)
{
    const float* gmean  = (const float*)d_in[0];
    const float* gfeat  = (const float*)d_in[1];
    const float* gvalid = (const float*)d_in[2];
    const float* gadj   = (const float*)d_in[3];
    float* out = (float*)d_out;

    cudaFuncSetAttribute(em_main, cudaFuncAttributeMaxDynamicSharedMemorySize,
                         SMEM_FLOATS * (int)sizeof(float));

    dim3 grid(CH, Bb);
    em_main<<<grid, 256, SMEM_FLOATS * sizeof(float)>>>(gmean, gfeat, gvalid, gadj);
    reduce1<<<(G1 * EM + G1 * ES + 255) / 256, 256>>>();
    reduce2<<<(EM + 255) / 256, 256>>>(out);
}

// round 7
// speedup vs baseline: 2.4531x; 2.4531x over previous
#include <cuda_runtime.h>

#define Bb 8
#define Nn 16384
#define Kk 256
#define Dd 20
#define DE 21            // Dd + folded msq row

#define TP 32            // pixels per tile (4 per warp, 8 warps)
#define PPB 128          // pixels per block
#define NTILES (PPB/TP)  // 4
#define CH (Nn/PPB)      // 128 chunks per batch

#define EM (Bb*Kk*Dd)    // 40960
#define ES (Bb*Kk)       // 2048
#define G1 8             // stage-1 reduction groups
#define CPG (CH/G1)      // 16 chunks per group

// Per-(chunk,batch,k) partials. Plain stores -> deterministic reductions.
__device__ float g_partM[(long)CH * EM];   // ~21 MB
__device__ float g_partS[CH * ES];         // ~1 MB
__device__ float g_p2M[G1 * EM];
__device__ float g_p2S[G1 * ES];

// layout: mean_ext(21*256=5376) f_sm(640) f_dup(1344) rinv(32) p_sm(8192) va(8192)
#define OFF_MEAN 0
#define OFF_FSM  (OFF_MEAN + DE*Kk)            // 5376
#define OFF_FDUP (OFF_FSM + TP*Dd)             // 6016
#define OFF_RINV (OFF_FDUP + TP*2*DE)          // 7360
#define OFF_PSM  (OFF_RINV + TP)               // 7392
#define OFF_VA   (OFF_PSM + TP*Kk)             // 15584
#define SMEM_FLOATS (OFF_VA + 8*2*2*Kk)        // 23776 floats = 95104 B

// ---- Blackwell packed f32x2 helpers ----
typedef unsigned long long u64;

__device__ __forceinline__ u64 pack2(float v) {          // broadcast {v,v}
    u64 r; asm("mov.b64 %0, {%1,%1};" : "=l"(r) : "f"(v)); return r;
}
__device__ __forceinline__ u64 ffma2(u64 a, u64 b, u64 c) {
    u64 d; asm("fma.rn.f32x2 %0, %1, %2, %3;" : "=l"(d) : "l"(a), "l"(b), "l"(c));
    return d;
}
__device__ __forceinline__ void unpk(u64 v, float& lo, float& hi) {
    asm("mov.b64 {%0,%1}, %2;" : "=f"(lo), "=f"(hi) : "l"(v));
}
__device__ __forceinline__ void cpasync16(float* smem_dst, const float* gsrc) {
    unsigned s = (unsigned)__cvta_generic_to_shared(smem_dst);
    asm volatile("cp.async.cg.shared.global [%0], [%1], 16;" :: "r"(s), "l"(gsrc));
}
__device__ __forceinline__ void cpasync_commit() {
    asm volatile("cp.async.commit_group;");
}
__device__ __forceinline__ void cpasync_wait0() {
    asm volatile("cp.async.wait_group 0;");
}

__global__ __launch_bounds__(256, 2)
void em_main(const float* __restrict__ gmean,
             const float* __restrict__ gfeat,
             const float* __restrict__ gvalid,
             const float* __restrict__ gadj)
{
    extern __shared__ float sm[];
    float* mean_sm = sm + OFF_MEAN;   // [DE][Kk]: rows 0..19 mean^T, row 20 = msq
    float* f_sm    = sm + OFF_FSM;    // [TP][Dd]    natural (Phase B)
    float* f_dup   = sm + OFF_FDUP;   // [TP][2*DE]  {f,f}; [2*Dd]={-.5,-.5}
    float* rinv_sm = sm + OFF_RINV;   // [TP]
    float* p_sm    = sm + OFF_PSM;    // [TP][Kk]    unnormalized e
    float* va_sm   = sm + OFF_VA;     // [8][2][2][Kk] per-warp px2/px3 v,a

    const int tid = threadIdx.x;
    const int kg  = tid & 31;          // lane
    const int w   = tid >> 5;          // warp 0..7; owns pixels 4w..4w+3
    const int b   = blockIdx.y;
    const int ch  = blockIdx.x;
    const int n0  = ch * PPB;

    // ---- stage mean[b] transposed [d][k]; row 20 = |m|^2 ----
    const float* mb = gmean + (long)b * Kk * Dd;
    for (int i = tid; i < Kk * Dd; i += 256) {
        int k = i / Dd, d = i - k * Dd;
        mean_sm[d * Kk + k] = mb[i];
    }
    __syncthreads();
    {
        float s = 0.f;
#pragma unroll
        for (int d = 0; d < Dd; d++) { float m = mean_sm[d * Kk + tid]; s += m * m; }
        mean_sm[Dd * Kk + tid] = s;    // msq row
    }

    // Phase-B accumulators: thread owns k = tid, packed pairs over d
    u64 macc2[Dd / 2];
#pragma unroll
    for (int q = 0; q < Dd / 2; q++) macc2[q] = 0ULL;
    float sacc = 0.f;

    for (int t = 0; t < NTILES; t++) {
        const int nbase = n0 + t * TP;
        __syncthreads();   // msq ready (t=0) / previous Phase B done

        // ---- cooperative feature-tile load; build duplicated copy ----
        if (tid < TP * Dd / 4) {
            float4 fv = ((const float4*)(gfeat + ((long)b * Nn + nbase) * Dd))[tid];
            ((float4*)f_sm)[tid] = fv;
            const int e0 = 4 * tid;
            const int px = e0 / Dd, d0 = e0 - px * Dd;   // float4 never spans pixels
            float* fd = &f_dup[px * (2 * DE) + 2 * d0];
            ((float2*)fd)[0] = make_float2(fv.x, fv.x);
            ((float2*)fd)[1] = make_float2(fv.y, fv.y);
            ((float2*)fd)[2] = make_float2(fv.z, fv.z);
            ((float2*)fd)[3] = make_float2(fv.w, fv.w);
        }
        if (tid < TP)   // msq coupling coefficient at d=20
            *(float2*)&f_dup[tid * (2 * DE) + 2 * Dd] = make_float2(-0.5f, -0.5f);
        __syncthreads();

        // ================= Phase A =================
        const int  p0   = 4 * w;
        const long rowb = ((long)b * Nn + nbase + p0) * Kk;
        const float* vr = gvalid + rowb;
        const float* ar = gadj   + rowb;

        // px0/px1 v/a into registers (hidden under dot loop)
        float4 v00 = *(const float4*)(vr + 4 * kg);
        float4 v01 = *(const float4*)(vr + 128 + 4 * kg);
        float4 a00 = *(const float4*)(ar + 4 * kg);
        float4 a01 = *(const float4*)(ar + 128 + 4 * kg);
        float4 v10 = *(const float4*)(vr + Kk + 4 * kg);
        float4 v11 = *(const float4*)(vr + Kk + 128 + 4 * kg);
        float4 a10 = *(const float4*)(ar + Kk + 4 * kg);
        float4 a11 = *(const float4*)(ar + Kk + 128 + 4 * kg);

        // px2/px3 v/a via cp.async into per-warp smem (hidden under dot loop)
#pragma unroll
        for (int j = 0; j < 2; j++) {
            const float* vrow = vr + (long)(2 + j) * Kk;
            const float* arow = ar + (long)(2 + j) * Kk;
            float* vdst = &va_sm[(((w * 2 + j) * 2 + 0) * Kk)];
            float* adst = &va_sm[(((w * 2 + j) * 2 + 1) * Kk)];
            cpasync16(vdst + 8 * kg,     vrow + 8 * kg);
            cpasync16(vdst + 8 * kg + 4, vrow + 8 * kg + 4);
            cpasync16(adst + 8 * kg,     arow + 8 * kg);
            cpasync16(adst + 8 * kg + 4, arow + 8 * kg + 4);
        }
        cpasync_commit();

        // fsq per pixel: lanes 0-3 compute, broadcast later via shfl
        float myfsq = 0.f;
        if (kg < 4) {
            const float* fr = &f_sm[(p0 + kg) * Dd];
#pragma unroll
            for (int d = 0; d < Dd; d++) myfsq = fmaf(fr[d], fr[d], myfsq);
        }

        // ---- packed dot over 4 px, 21 d (msq folded at d=20) ----
        u64 dot2[4][4];
#pragma unroll
        for (int p = 0; p < 4; p++)
#pragma unroll
            for (int j = 0; j < 4; j++) dot2[p][j] = 0ULL;

#pragma unroll
        for (int d = 0; d < DE; d++) {
            ulonglong2 m0 = *(const ulonglong2*)&mean_sm[d * Kk + 4 * kg];
            ulonglong2 m1 = *(const ulonglong2*)&mean_sm[d * Kk + 128 + 4 * kg];
#pragma unroll
            for (int p = 0; p < 4; p++) {
                const u64 ff = *(const u64*)&f_dup[(p0 + p) * (2 * DE) + 2 * d];
                dot2[p][0] = ffma2(m0.x, ff, dot2[p][0]);
                dot2[p][1] = ffma2(m0.y, ff, dot2[p][1]);
                dot2[p][2] = ffma2(m1.x, ff, dot2[p][2]);
                dot2[p][3] = ffma2(m1.y, ff, dot2[p][3]);
            }
        }

        float s4[4];

        // ---- epilogues px0, px1 (register v/a) ----
#pragma unroll
        for (int p = 0; p < 2; p++) {
            float va[8], aa[8];
            if (p == 0) {
                va[0]=v00.x; va[1]=v00.y; va[2]=v00.z; va[3]=v00.w;
                va[4]=v01.x; va[5]=v01.y; va[6]=v01.z; va[7]=v01.w;
                aa[0]=a00.x; aa[1]=a00.y; aa[2]=a00.z; aa[3]=a00.w;
                aa[4]=a01.x; aa[5]=a01.y; aa[6]=a01.z; aa[7]=a01.w;
            } else {
                va[0]=v10.x; va[1]=v10.y; va[2]=v10.z; va[3]=v10.w;
                va[4]=v11.x; va[5]=v11.y; va[6]=v11.z; va[7]=v11.w;
                aa[0]=a10.x; aa[1]=a10.y; aa[2]=a10.z; aa[3]=a10.w;
                aa[4]=a11.x; aa[5]=a11.y; aa[6]=a11.z; aa[7]=a11.w;
            }
            const float c = __shfl_sync(0xffffffffu, myfsq, p);
            float dv[8];
            unpk(dot2[p][0], dv[0], dv[1]);
            unpk(dot2[p][1], dv[2], dv[3]);
            unpk(dot2[p][2], dv[4], dv[5]);
            unpk(dot2[p][3], dv[6], dv[7]);
            float e[8];
            float s = 0.f;
#pragma unroll
            for (int j = 0; j < 8; j++) {
                float dist = fmaf(-2.f, dv[j], c);          // msq folded into dot
                e[j] = __expf(fmaf(dist, -va[j], -aa[j]));
                s += e[j];
            }
            s4[p] = s;
            *(float4*)&p_sm[(p0 + p) * Kk + 4 * kg] = make_float4(e[0], e[1], e[2], e[3]);
            *(float4*)&p_sm[(p0 + p) * Kk + 128 + 4 * kg] = make_float4(e[4], e[5], e[6], e[7]);
        }

        // ---- epilogues px2, px3 (smem v/a via cp.async) ----
        cpasync_wait0();
#pragma unroll
        for (int j = 0; j < 2; j++) {
            const int p = 2 + j;
            const float* vbase = &va_sm[(((w * 2 + j) * 2 + 0) * Kk)];
            const float* abase = &va_sm[(((w * 2 + j) * 2 + 1) * Kk)];
            float4 vv0 = *(const float4*)&vbase[4 * kg];
            float4 vv1 = *(const float4*)&vbase[128 + 4 * kg];
            float4 av0 = *(const float4*)&abase[4 * kg];
            float4 av1 = *(const float4*)&abase[128 + 4 * kg];
            float va[8] = {vv0.x, vv0.y, vv0.z, vv0.w, vv1.x, vv1.y, vv1.z, vv1.w};
            float aa[8] = {av0.x, av0.y, av0.z, av0.w, av1.x, av1.y, av1.z, av1.w};

            const float c = __shfl_sync(0xffffffffu, myfsq, p);
            float dv[8];
            unpk(dot2[p][0], dv[0], dv[1]);
            unpk(dot2[p][1], dv[2], dv[3]);
            unpk(dot2[p][2], dv[4], dv[5]);
            unpk(dot2[p][3], dv[6], dv[7]);
            float e[8];
            float s = 0.f;
#pragma unroll
            for (int jj = 0; jj < 8; jj++) {
                float dist = fmaf(-2.f, dv[jj], c);
                e[jj] = __expf(fmaf(dist, -va[jj], -aa[jj]));
                s += e[jj];
            }
            s4[p] = s;
            *(float4*)&p_sm[(p0 + p) * Kk + 4 * kg] = make_float4(e[0], e[1], e[2], e[3]);
            *(float4*)&p_sm[(p0 + p) * Kk + 128 + 4 * kg] = make_float4(e[4], e[5], e[6], e[7]);
        }

        // 4 interleaved butterfly sums
#pragma unroll
        for (int o = 16; o > 0; o >>= 1) {
            s4[0] += __shfl_xor_sync(0xffffffffu, s4[0], o);
            s4[1] += __shfl_xor_sync(0xffffffffu, s4[1], o);
            s4[2] += __shfl_xor_sync(0xffffffffu, s4[2], o);
            s4[3] += __shfl_xor_sync(0xffffffffu, s4[3], o);
        }
        if (kg < 4) {
            float sv = (kg == 0) ? s4[0] : (kg == 1) ? s4[1] : (kg == 2) ? s4[2] : s4[3];
            rinv_sm[p0 + kg] = __fdividef(1.f, sv);
        }
        __syncthreads();

        // ============ Phase B: accumulate M[k][:] and S[k] (packed) ============
#pragma unroll
        for (int p4 = 0; p4 < TP / 4; p4++) {
            const float4 rv = *(const float4*)&rinv_sm[4 * p4];
            const float rvs[4] = {rv.x, rv.y, rv.z, rv.w};
#pragma unroll
            for (int pi = 0; pi < 4; pi++) {
                const int p = 4 * p4 + pi;
                const float pv = p_sm[p * Kk + tid] * rvs[pi];
                sacc += pv;
                const u64 pp = pack2(pv);
                const ulonglong2* f2 = (const ulonglong2*)&f_sm[p * Dd];
#pragma unroll
                for (int q = 0; q < 5; q++) {
                    ulonglong2 u = f2[q];
                    macc2[2 * q]     = ffma2(u.x, pp, macc2[2 * q]);
                    macc2[2 * q + 1] = ffma2(u.y, pp, macc2[2 * q + 1]);
                }
            }
        }
    }

    // ---- coalesced per-(chunk,b,k) partials ----
    const int bk = (b << 8) | tid;            // b*Kk + k
    g_partS[ch * ES + bk] = sacc;
    float* pm = &g_partM[(long)ch * EM + (long)bk * Dd];
#pragma unroll
    for (int q = 0; q < Dd / 2; q++) {
        float lo, hi;
        unpk(macc2[q], lo, hi);
        pm[2 * q] = lo;  pm[2 * q + 1] = hi;
    }
}

// Stage 1: fold 128 chunks -> 8 groups, fully coalesced (thread = element).
__global__ void reduce1()
{
    const int i = blockIdx.x * 256 + threadIdx.x;
    if (i < G1 * EM) {
        const int g = i / EM, e = i - g * EM;
        float s = 0.f;
#pragma unroll 4
        for (int c = 0; c < CPG; c++)
            s += g_partM[(long)(g * CPG + c) * EM + e];
        g_p2M[i] = s;
    } else {
        const int j = i - G1 * EM;
        if (j < G1 * ES) {
            const int g = j / ES, e = j - g * ES;
            float s = 0.f;
#pragma unroll 4
            for (int c = 0; c < CPG; c++)
                s += g_partS[(g * CPG + c) * ES + e];
            g_p2S[j] = s;
        }
    }
}

// Stage 2: final 8-way sum + normalize.
__global__ void reduce2(float* __restrict__ out)
{
    const int e = blockIdx.x * 256 + threadIdx.x;   // over EM = 40960
    if (e >= EM) return;
    const int bk = e / Dd;
    float m = 0.f, s = 0.f;
#pragma unroll
    for (int g = 0; g < G1; g++) {
        m += g_p2M[g * EM + e];
        s += g_p2S[g * ES + bk];
    }
    out[e] = m / fmaxf(s, 1e-12f);
}

extern "C" void kernel_launch(void* const* d_in, const int* in_sizes, int n_in,
                              void* d_out, int out_size)
{
    const float* gmean  = (const float*)d_in[0];
    const float* gfeat  = (const float*)d_in[1];
    const float* gvalid = (const float*)d_in[2];
    const float* gadj   = (const float*)d_in[3];
    float* out = (float*)d_out;

    cudaFuncSetAttribute(em_main, cudaFuncAttributeMaxDynamicSharedMemorySize,
                         SMEM_FLOATS * (int)sizeof(float));

    dim3 grid(CH, Bb);
    em_main<<<grid, 256, SMEM_FLOATS * sizeof(float)>>>(gmean, gfeat, gvalid, gadj);
    reduce1<<<(G1 * EM + G1 * ES + 255) / 256, 256>>>();
    reduce2<<<(EM + 255) / 256, 256>>>(out);
}